// round 4
// baseline (speedup 1.0000x reference)
#include <cuda_runtime.h>
#include <math.h>

// ReacPartialGbModel: B=4096 RK4 integrations, T=256 steps.
// r1(x0), r2(x1) scalar MLPs -> cubic-Hermite LUTs with the ODE affine terms
// folded in:  A(x0)=(0.1*Ca+r1)/0.3, R(x0)=r1/0.2, B(x1)=(0.1*Cb+3*r2)/0.2
//   k0 = Caf/3 - A(x0);  k1 = R(x0) - B(x1) + r3/0.2
// r3 (24->32->32->1) evaluated 3x/step (k2/k3 share z23 = (z1+z4)/2), all from
// start-of-step state -> 3 interleaved ILP chains, packed f32x2 FMAs,
// 4-instr exact tanh (weights prescaled by 2*log2e), register ring via
// unroll-8. One warp per batch element; lane = hidden unit.

namespace {

constexpr int kT = 256;
constexpr int kB = 4096;
constexpr int kN = 8192;
constexpr float kLo   = -64.0f;
constexpr float kH    = 128.0f / kN;   // 1/64
constexpr float kInvH = kN / 128.0f;   // 64
constexpr float kSc   = 2.885390081777927f;  // 2*log2(e)

__device__ float2 g_nA[kN + 1];
__device__ float2 g_nR[kN + 1];
__device__ float2 g_nB[kN + 1];
__device__ __align__(16) float4 g_lutX[2 * kN];   // [2i]=A, [2i+1]=R
__device__ __align__(16) float4 g_lutY[kN];       // B

// ---------------- helpers ---------------------------------------------------
__device__ __forceinline__ float tanh_acc(float x) {   // build-time, ~1e-7
    float ax = fabsf(x);
    float e  = __expf(-2.0f * ax);
    float r  = __fdividef(1.0f - e, 1.0f + e);
    return copysignf(r, x);
}

// main-kernel tanh: input already prescaled by 2*log2e
__device__ __forceinline__ float tanh_pre(float a) {
    float e; asm("ex2.approx.f32 %0, %1;" : "=f"(e) : "f"(a));
    float s = e + 1.0f;
    float r; asm("rcp.approx.f32 %0, %1;" : "=f"(r) : "f"(s));
    return fmaf(-2.0f, r, 1.0f);
}

typedef unsigned long long ull;
__device__ __forceinline__ ull fma2(ull a, ull b, ull c) {
    ull d; asm("fma.rn.f32x2 %0, %1, %2, %3;" : "=l"(d) : "l"(a), "l"(b), "l"(c));
    return d;
}
__device__ __forceinline__ ull pk(float lo, float hi) {
    ull d; asm("mov.b64 %0, {%1, %2};" : "=l"(d) : "f"(lo), "f"(hi));
    return d;
}
__device__ __forceinline__ float upadd(ull v) {
    float lo, hi; asm("mov.b64 {%0, %1}, %2;" : "=f"(lo), "=f"(hi) : "l"(v));
    return lo + hi;
}

// ---------------- build kernel 1: node values + derivatives -----------------
__global__ void build_nodes(const float* __restrict__ W0, const float* __restrict__ B0,
                            const float* __restrict__ W1, const float* __restrict__ B1,
                            const float* __restrict__ W2, const float* __restrict__ B2,
                            const float* __restrict__ V0, const float* __restrict__ C0,
                            const float* __restrict__ V1, const float* __restrict__ C1,
                            const float* __restrict__ V2, const float* __restrict__ C2)
{
    int idx = blockIdx.x * blockDim.x + threadIdx.x;
    if (idx >= 2 * (kN + 1)) return;
    int net  = idx / (kN + 1);
    int node = idx - net * (kN + 1);
    const float* w0 = net ? V0 : W0;  const float* b0 = net ? C0 : B0;
    const float* w1 = net ? V1 : W1;  const float* b1 = net ? C1 : B1;
    const float* w2 = net ? V2 : W2;  const float* b2 = net ? C2 : B2;

    float x = kLo + node * kH;
    float t0[32], s0[32];
#pragma unroll
    for (int i = 0; i < 32; ++i) {
        float a  = fmaf(w0[i], x, b0[i]);
        float th = tanh_acc(a);
        t0[i] = th;
        s0[i] = (1.0f - th * th) * w0[i];
    }
    float y = b2[0], d = 0.0f;
    for (int j = 0; j < 32; ++j) {
        float a = b1[j], da = 0.0f;
#pragma unroll
        for (int i = 0; i < 32; ++i) {
            float w = w1[i * 32 + j];
            a  = fmaf(t0[i], w, a);
            da = fmaf(s0[i], w, da);
        }
        float th = tanh_acc(a);
        y = fmaf(w2[j], th, y);
        d = fmaf(w2[j] * (1.0f - th * th), da, d);
    }
    if (net == 0) {
        y *= 0.3f; d *= 0.3f;   // r1 = fnn*Castd
        float A  = (0.1f * fmaf(0.3f, x, 0.5f) + y) * (1.0f / 0.3f);
        float Ad = (0.03f + d) * (1.0f / 0.3f);
        g_nA[node] = make_float2(A, Ad);
        g_nR[node] = make_float2(y * 5.0f, d * 5.0f);
    } else {
        y *= 0.2f; d *= 0.2f;   // r2 = fnn*Cbstd
        float Bv = (0.1f * fmaf(0.2f, x, 0.5f) + 3.0f * y) * 5.0f;
        float Bd = (0.02f + 3.0f * d) * 5.0f;
        g_nB[node] = make_float2(Bv, Bd);
    }
}

// ---------------- build kernel 2: Hermite -> cubic coefficients -------------
__device__ __forceinline__ float4 hermite(float2 n0, float2 n1) {
    float hd0 = kH * n0.y, hd1 = kH * n1.y;
    float dy  = n1.x - n0.x;
    return make_float4(n0.x, hd0,
                       3.0f * dy - 2.0f * hd0 - hd1,
                       -2.0f * dy + hd0 + hd1);
}

__global__ void build_coeffs()
{
    int i = blockIdx.x * blockDim.x + threadIdx.x;
    if (i >= kN) return;
    g_lutX[2 * i]     = hermite(g_nA[i], g_nA[i + 1]);
    g_lutX[2 * i + 1] = hermite(g_nR[i], g_nR[i + 1]);
    g_lutY[i]         = hermite(g_nB[i], g_nB[i + 1]);
}

// ---------------- main kernel ------------------------------------------------
__global__ void __launch_bounds__(128, 3)
rk4_kernel(const float* __restrict__ useq, const float* __restrict__ xz0,
           const float* __restrict__ r3W0, const float* __restrict__ r3b0,
           const float* __restrict__ r3W1, const float* __restrict__ r3b1,
           const float* __restrict__ r3W2, const float* __restrict__ r3b2,
           float* __restrict__ out)
{
    const int wslot = threadIdx.x >> 5;
    const int wid   = blockIdx.x * 4 + wslot;
    const int lane  = threadIdx.x & 31;

    __shared__ __align__(16) float sbuf[4][192];   // 2 x 96 per warp (parity)

    // ---- p3 weights, prescaled by 2*log2e, packed pairs --------------------
    ull w30p[8], w31p[16];
    float wu[8];
#pragma unroll
    for (int j = 0; j < 8; ++j)
        w30p[j] = pk(r3W0[(2 * j) * 32 + lane] * kSc,
                     r3W0[(2 * j + 1) * 32 + lane] * kSc);
#pragma unroll
    for (int k = 0; k < 8; ++k) wu[k] = r3W0[(16 + k) * 32 + lane] * kSc;
#pragma unroll
    for (int j = 0; j < 16; ++j)
        w31p[j] = pk(r3W1[(2 * j) * 32 + lane] * kSc,
                     r3W1[(2 * j + 1) * 32 + lane] * kSc);
    const float b30s = r3b0[lane] * kSc;
    const ull   b31p = pk(r3b1[lane] * kSc, 0.0f);
    const float w32  = r3W2[lane], b32 = r3b2[0];

    const float4* lutX = g_lutX;
    const float4* lutY = g_lutY;

    // ---- state: x scalar, history as packed register ring ------------------
    const float* xz = xz0 + wid * 26;
    float x0 = xz[0], x1 = xz[1];
    ull xq[8];
    float up[8];
#pragma unroll
    for (int j = 0; j < 8; ++j) xq[j] = pk(xz[2 + 2 * j], xz[3 + 2 * j]);
#pragma unroll
    for (int k = 0; k < 8; ++k) up[k] = xz[18 + k];

    const float4* uptr4 = reinterpret_cast<const float4*>(useq + wid * kT);
    float2* outp = reinterpret_cast<float2*>(out) + wid * kT;

    auto kof = [&](float xa0, float xa1, float r3s, float cafs,
                   float& k0, float& k1v) {
        float xf0 = fmaf(xa0, kInvH, (float)(kN / 2));
        float f0  = fminf(fmaxf(floorf(xf0), 0.0f), (float)(kN - 1));
        float t0  = xf0 - f0;
        int   i0  = (int)f0;
        float4 cA = __ldg(&lutX[2 * i0]);
        float4 cR = __ldg(&lutX[2 * i0 + 1]);
        float xf1 = fmaf(xa1, kInvH, (float)(kN / 2));
        float f1  = fminf(fmaxf(floorf(xf1), 0.0f), (float)(kN - 1));
        float t1  = xf1 - f1;
        int   i1  = (int)f1;
        float4 cB = __ldg(&lutY[i1]);
        float A  = fmaf(fmaf(fmaf(cA.w, t0, cA.z), t0, cA.y), t0, cA.x);
        float R  = fmaf(fmaf(fmaf(cR.w, t0, cR.z), t0, cR.y), t0, cR.x);
        float Bv = fmaf(fmaf(fmaf(cB.w, t1, cB.z), t1, cB.y), t1, cB.x);
        k0  = cafs - A;
        k1v = R - Bv + r3s;
    };

#pragma unroll 1
    for (int tb = 0; tb < kT; tb += 8) {
        float4 ua = __ldg(uptr4 + (tb >> 2));
        float4 ub = __ldg(uptr4 + (tb >> 2) + 1);
        float uu[8] = {ua.x, ua.y, ua.z, ua.w, ub.x, ub.y, ub.z, ub.w};

#pragma unroll
        for (int p = 0; p < 8; ++p) {
            const float u = uu[p];
            if (lane == 0) outp[tb + p] = make_float2(x0, x1);
            const float cafs = fmaf(u, 0.5f / 3.0f, 1.0f / 3.0f);

            // ---- p3 layer-0 shared sub-dots (packed) -----------------------
            ull px = pk(x0, x1);
            ull S1 = 0ull, S4 = 0ull;
#pragma unroll
            for (int j = 0; j < 8; ++j)
                S1 = fma2(xq[(p + j) & 7], w30p[j], S1);
#pragma unroll
            for (int j = 0; j < 7; ++j)
                S4 = fma2(xq[(p + j + 1) & 7], w30p[j], S4);
            S4 = fma2(px, w30p[7], S4);
            float Ua = b30s, Ub = 0.0f;
#pragma unroll
            for (int k = 0; k < 8; k += 2) {
                Ua = fmaf(up[(p + k) & 7],     wu[k],     Ua);
                Ub = fmaf(up[(p + k + 1) & 7], wu[k + 1], Ub);
            }
            float S1s = upadd(S1), S4s = upadd(S4), Us = Ua + Ub;
            float a3_1  = S1s + Us;
            float a3_4  = S4s + Us;
            float a3_23 = fmaf(0.5f, S1s + S4s, Us);

            // ---- three p3 evals, interleaved -------------------------------
            float h1 = tanh_pre(a3_1);
            float h2 = tanh_pre(a3_23);
            float h3 = tanh_pre(a3_4);
            float* buf = sbuf[wslot] + (p & 1) * 96;
            buf[lane]      = h1;
            buf[32 + lane] = h2;
            buf[64 + lane] = h3;
            __syncwarp();
            ull C1 = b31p, C2 = b31p, C3 = b31p;
            const ulonglong2* bq = reinterpret_cast<const ulonglong2*>(buf);
#pragma unroll
            for (int q = 0; q < 8; ++q) {
                ulonglong2 v1 = bq[q];
                C1 = fma2(v1.x, w31p[2 * q],     C1);
                C1 = fma2(v1.y, w31p[2 * q + 1], C1);
                ulonglong2 v2 = bq[8 + q];
                C2 = fma2(v2.x, w31p[2 * q],     C2);
                C2 = fma2(v2.y, w31p[2 * q + 1], C2);
                ulonglong2 v3 = bq[16 + q];
                C3 = fma2(v3.x, w31p[2 * q],     C3);
                C3 = fma2(v3.y, w31p[2 * q + 1], C3);
            }
            float p1 = tanh_pre(upadd(C1)) * w32;
            float p2 = tanh_pre(upadd(C2)) * w32;
            float p3 = tanh_pre(upadd(C3)) * w32;
#pragma unroll
            for (int m = 16; m > 0; m >>= 1) {
                p1 += __shfl_xor_sync(0xffffffffu, p1, m);
                p2 += __shfl_xor_sync(0xffffffffu, p2, m);
                p3 += __shfl_xor_sync(0xffffffffu, p3, m);
            }
            float r3s1  = p1 + b32;   // r3/0.2 (the 0.2 cancels)
            float r3s23 = p2 + b32;
            float r3s4  = p3 + b32;

            // ---- RK4 k-chain (folded LUTs) ---------------------------------
            float k10, k11; kof(x0, x1, r3s1, cafs, k10, k11);
            float xb0 = fmaf(0.5f, k10, x0), xb1 = fmaf(0.5f, k11, x1);
            float k20, k21; kof(xb0, xb1, r3s23, cafs, k20, k21);
            float xc0 = fmaf(0.5f, k20, x0), xc1 = fmaf(0.5f, k21, x1);
            float k30, k31; kof(xc0, xc1, r3s23, cafs, k30, k31);
            float xd0 = x0 + k30, xd1 = x1 + k31;
            float k40, k41; kof(xd0, xd1, r3s4, cafs, k40, k41);

            float nx0 = fmaf(k10 + 2.0f * (k20 + k30) + k40, 1.0f / 6.0f, x0);
            float nx1 = fmaf(k11 + 2.0f * (k21 + k31) + k41, 1.0f / 6.0f, x1);

            // ---- ring update (no shifts) -----------------------------------
            xq[p & 7] = px;
            up[p & 7] = u;
            x0 = nx0; x1 = nx1;
        }
    }
}

}  // namespace

extern "C" void kernel_launch(void* const* d_in, const int* in_sizes, int n_in,
                              void* d_out, int out_size) {
    (void)in_sizes; (void)n_in; (void)out_size;
    const float* useq = (const float*)d_in[0];
    const float* xz0  = (const float*)d_in[1];
    const float* r1W0 = (const float*)d_in[2];
    const float* r1b0 = (const float*)d_in[3];
    const float* r1W1 = (const float*)d_in[4];
    const float* r1b1 = (const float*)d_in[5];
    const float* r1W2 = (const float*)d_in[6];
    const float* r1b2 = (const float*)d_in[7];
    const float* r2W0 = (const float*)d_in[8];
    const float* r2b0 = (const float*)d_in[9];
    const float* r2W1 = (const float*)d_in[10];
    const float* r2b1 = (const float*)d_in[11];
    const float* r2W2 = (const float*)d_in[12];
    const float* r2b2 = (const float*)d_in[13];
    const float* r3W0 = (const float*)d_in[14];
    const float* r3b0 = (const float*)d_in[15];
    const float* r3W1 = (const float*)d_in[16];
    const float* r3b1 = (const float*)d_in[17];
    const float* r3W2 = (const float*)d_in[18];
    const float* r3b2 = (const float*)d_in[19];
    float* out = (float*)d_out;

    build_nodes<<<(2 * (kN + 1) + 127) / 128, 128>>>(
        r1W0, r1b0, r1W1, r1b1, r1W2, r1b2,
        r2W0, r2b0, r2W1, r2b1, r2W2, r2b2);
    build_coeffs<<<(kN + 127) / 128, 128>>>();
    rk4_kernel<<<kB / 4, 128>>>(useq, xz0,
                                r3W0, r3b0, r3W1, r3b1, r3W2, r3b2,
                                out);
}

// round 6
// speedup vs baseline: 1.0353x; 1.0353x over previous
#include <cuda_runtime.h>
#include <math.h>

// ReacPartialGbModel: B=4096 RK4 integrations, T=256 steps.
// r1(x0), r2(x1) -> cubic-Hermite LUTs with ODE affine terms folded in.
// r3 evaluated 3x/step; software-pipelined: the k1-stage r3 of step t+1 is
// computed during step t (depends only on history + x_t), so kof stage 1
// starts immediately at step entry. S1_{t+1} = S4_t reused. History-part of
// S4 precomputed off-path. Critical reduction (r3s23) via smem tree; the two
// off-path reductions via shfl butterflies. One warp per batch element.

namespace {

constexpr int kT = 256;
constexpr int kB = 4096;
constexpr int kN = 8192;
constexpr float kLo   = -64.0f;
constexpr float kH    = 128.0f / kN;   // 1/64
constexpr float kInvH = kN / 128.0f;   // 64
constexpr float kSc   = 2.885390081777927f;  // 2*log2(e)

__device__ float2 g_nA[kN + 1];
__device__ float2 g_nR[kN + 1];
__device__ float2 g_nB[kN + 1];
__device__ __align__(16) float4 g_lutX[2 * kN];   // [2i]=A, [2i+1]=R
__device__ __align__(16) float4 g_lutY[kN];       // B

// ---------------- helpers ---------------------------------------------------
__device__ __forceinline__ float tanh_acc(float x) {   // build-time, ~1e-7
    float ax = fabsf(x);
    float e  = __expf(-2.0f * ax);
    float r  = __fdividef(1.0f - e, 1.0f + e);
    return copysignf(r, x);
}

// main-kernel tanh: input already prescaled by 2*log2e
__device__ __forceinline__ float tanh_pre(float a) {
    float e; asm("ex2.approx.f32 %0, %1;" : "=f"(e) : "f"(a));
    float s = e + 1.0f;
    float r; asm("rcp.approx.f32 %0, %1;" : "=f"(r) : "f"(s));
    return fmaf(-2.0f, r, 1.0f);
}

typedef unsigned long long ull;
__device__ __forceinline__ ull fma2(ull a, ull b, ull c) {
    ull d; asm("fma.rn.f32x2 %0, %1, %2, %3;" : "=l"(d) : "l"(a), "l"(b), "l"(c));
    return d;
}
__device__ __forceinline__ ull add2(ull a, ull b) {
    ull d; asm("add.rn.f32x2 %0, %1, %2;" : "=l"(d) : "l"(a), "l"(b));
    return d;
}
__device__ __forceinline__ ull pk(float lo, float hi) {
    ull d; asm("mov.b64 %0, {%1, %2};" : "=l"(d) : "f"(lo), "f"(hi));
    return d;
}
__device__ __forceinline__ float upadd(ull v) {
    float lo, hi; asm("mov.b64 {%0, %1}, %2;" : "=f"(lo), "=f"(hi) : "l"(v));
    return lo + hi;
}
__device__ __forceinline__ float bfly(float v) {
#pragma unroll
    for (int m = 16; m > 0; m >>= 1) v += __shfl_xor_sync(0xffffffffu, v, m);
    return v;
}

// ---------------- build kernel 1: node values + derivatives -----------------
__global__ void build_nodes(const float* __restrict__ W0, const float* __restrict__ B0,
                            const float* __restrict__ W1, const float* __restrict__ B1,
                            const float* __restrict__ W2, const float* __restrict__ B2,
                            const float* __restrict__ V0, const float* __restrict__ C0,
                            const float* __restrict__ V1, const float* __restrict__ C1,
                            const float* __restrict__ V2, const float* __restrict__ C2)
{
    int idx = blockIdx.x * blockDim.x + threadIdx.x;
    if (idx >= 2 * (kN + 1)) return;
    int net  = idx / (kN + 1);
    int node = idx - net * (kN + 1);
    const float* w0 = net ? V0 : W0;  const float* b0 = net ? C0 : B0;
    const float* w1 = net ? V1 : W1;  const float* b1 = net ? C1 : B1;
    const float* w2 = net ? V2 : W2;  const float* b2 = net ? C2 : B2;

    float x = kLo + node * kH;
    float t0[32], s0[32];
#pragma unroll
    for (int i = 0; i < 32; ++i) {
        float a  = fmaf(w0[i], x, b0[i]);
        float th = tanh_acc(a);
        t0[i] = th;
        s0[i] = (1.0f - th * th) * w0[i];
    }
    float y = b2[0], d = 0.0f;
    for (int j = 0; j < 32; ++j) {
        float a = b1[j], da = 0.0f;
#pragma unroll
        for (int i = 0; i < 32; ++i) {
            float w = w1[i * 32 + j];
            a  = fmaf(t0[i], w, a);
            da = fmaf(s0[i], w, da);
        }
        float th = tanh_acc(a);
        y = fmaf(w2[j], th, y);
        d = fmaf(w2[j] * (1.0f - th * th), da, d);
    }
    if (net == 0) {
        y *= 0.3f; d *= 0.3f;   // r1 = fnn*Castd
        float A  = (0.1f * fmaf(0.3f, x, 0.5f) + y) * (1.0f / 0.3f);
        float Ad = (0.03f + d) * (1.0f / 0.3f);
        g_nA[node] = make_float2(A, Ad);
        g_nR[node] = make_float2(y * 5.0f, d * 5.0f);
    } else {
        y *= 0.2f; d *= 0.2f;   // r2 = fnn*Cbstd
        float Bv = (0.1f * fmaf(0.2f, x, 0.5f) + 3.0f * y) * 5.0f;
        float Bd = (0.02f + 3.0f * d) * 5.0f;
        g_nB[node] = make_float2(Bv, Bd);
    }
}

// ---------------- build kernel 2: Hermite -> cubic coefficients -------------
__device__ __forceinline__ float4 hermite(float2 n0, float2 n1) {
    float hd0 = kH * n0.y, hd1 = kH * n1.y;
    float dy  = n1.x - n0.x;
    return make_float4(n0.x, hd0,
                       3.0f * dy - 2.0f * hd0 - hd1,
                       -2.0f * dy + hd0 + hd1);
}

__global__ void build_coeffs()
{
    int i = blockIdx.x * blockDim.x + threadIdx.x;
    if (i >= kN) return;
    g_lutX[2 * i]     = hermite(g_nA[i], g_nA[i + 1]);
    g_lutX[2 * i + 1] = hermite(g_nR[i], g_nR[i + 1]);
    g_lutY[i]         = hermite(g_nB[i], g_nB[i + 1]);
}

// ---------------- main kernel ------------------------------------------------
__global__ void __launch_bounds__(128, 4)
rk4_kernel(const float* __restrict__ useq, const float* __restrict__ xz0,
           const float* __restrict__ r3W0, const float* __restrict__ r3b0,
           const float* __restrict__ r3W1, const float* __restrict__ r3b1,
           const float* __restrict__ r3W2, const float* __restrict__ r3b2,
           float* __restrict__ out)
{
    const int wslot = threadIdx.x >> 5;
    const int wid   = blockIdx.x * 4 + wslot;
    const int lane  = threadIdx.x & 31;

    // per warp: 2x96 parity h-broadcast + 32 q-reduction
    __shared__ __align__(16) float sbuf[4][224];

    // ---- p3 weights, prescaled by 2*log2e, packed pairs --------------------
    ull w30p[8], w31p[16];
    float wu[8];
#pragma unroll
    for (int j = 0; j < 8; ++j)
        w30p[j] = pk(r3W0[(2 * j) * 32 + lane] * kSc,
                     r3W0[(2 * j + 1) * 32 + lane] * kSc);
#pragma unroll
    for (int k = 0; k < 8; ++k) wu[k] = r3W0[(16 + k) * 32 + lane] * kSc;
#pragma unroll
    for (int j = 0; j < 16; ++j)
        w31p[j] = pk(r3W1[(2 * j) * 32 + lane] * kSc,
                     r3W1[(2 * j + 1) * 32 + lane] * kSc);
    const float b30s = r3b0[lane] * kSc;
    const ull   b31p = pk(r3b1[lane] * kSc, 0.0f);
    const float w32  = r3W2[lane], b32 = r3b2[0];

    const float4* lutX = g_lutX;
    const float4* lutY = g_lutY;

    // ---- state: x scalar, history as packed register ring ------------------
    const float* xz = xz0 + wid * 26;
    float x0 = xz[0], x1 = xz[1];
    ull xq[8];
    float up[8];
#pragma unroll
    for (int j = 0; j < 8; ++j) xq[j] = pk(xz[2 + 2 * j], xz[3 + 2 * j]);
#pragma unroll
    for (int k = 0; k < 8; ++k) up[k] = xz[18 + k];

    const float4* uptr4 = reinterpret_cast<const float4*>(useq + wid * kT);
    float2* outp = reinterpret_cast<float2*>(out) + wid * kT;

    auto kof = [&](float xa0, float xa1, float r3s, float cafs,
                   float& k0, float& k1v) {
        float xf0 = fmaf(xa0, kInvH, (float)(kN / 2));
        float f0  = fminf(fmaxf(floorf(xf0), 0.0f), (float)(kN - 1));
        float t0  = xf0 - f0;
        int   i0  = (int)f0;
        float4 cA = __ldg(&lutX[2 * i0]);
        float4 cR = __ldg(&lutX[2 * i0 + 1]);
        float xf1 = fmaf(xa1, kInvH, (float)(kN / 2));
        float f1  = fminf(fmaxf(floorf(xf1), 0.0f), (float)(kN - 1));
        float t1  = xf1 - f1;
        int   i1  = (int)f1;
        float4 cB = __ldg(&lutY[i1]);
        float A  = fmaf(fmaf(fmaf(cA.w, t0, cA.z), t0, cA.y), t0, cA.x);
        float R  = fmaf(fmaf(fmaf(cR.w, t0, cR.z), t0, cR.y), t0, cR.x);
        float Bv = fmaf(fmaf(fmaf(cB.w, t1, cB.z), t1, cB.y), t1, cB.x);
        k0  = cafs - A;
        k1v = R - Bv + r3s;
    };

    // ---- pipeline bootstrap (step 0, ring phase p=0) ------------------------
    float S1s, Uc, r3s1;
    {
        ull S1 = 0ull;
#pragma unroll
        for (int j = 0; j < 8; ++j) S1 = fma2(xq[j], w30p[j], S1);
        float Ua = b30s, Ub = 0.0f;
#pragma unroll
        for (int k = 0; k < 8; k += 2) {
            Ua = fmaf(up[k],     wu[k],     Ua);
            Ub = fmaf(up[k + 1], wu[k + 1], Ub);
        }
        S1s = upadd(S1);
        Uc  = Ua + Ub;
        // single r3 eval via broadcast + butterfly (latency-uncritical)
        float h = tanh_pre(S1s + Uc);
        sbuf[wslot][lane] = h;
        __syncwarp();
        ull C = b31p;
        const ulonglong2* bq = reinterpret_cast<const ulonglong2*>(sbuf[wslot]);
#pragma unroll
        for (int q = 0; q < 8; ++q) {
            ulonglong2 v = bq[q];
            C = fma2(v.x, w31p[2 * q],     C);
            C = fma2(v.y, w31p[2 * q + 1], C);
        }
        __syncwarp();
        r3s1 = bfly(tanh_pre(upadd(C)) * w32) + b32;
    }
    // history part of S4 for step p=0: slots (1+j), j=0..6
    ull S4p = 0ull;
#pragma unroll
    for (int j = 0; j < 7; ++j) S4p = fma2(xq[(1 + j) & 7], w30p[j], S4p);

#pragma unroll 1
    for (int tb = 0; tb < kT; tb += 8) {
        float4 ua = __ldg(uptr4 + (tb >> 2));
        float4 ub = __ldg(uptr4 + (tb >> 2) + 1);
        float uu[8] = {ua.x, ua.y, ua.z, ua.w, ub.x, ub.y, ub.z, ub.w};

#pragma unroll
        for (int p = 0; p < 8; ++p) {
            const float u = uu[p];
            if (lane == 0) outp[tb + p] = make_float2(x0, x1);
            const float cafs = fmaf(u, 0.5f / 3.0f, 1.0f / 3.0f);

            // ---- fast a3 computation (short path after x arrives) ----------
            ull px = pk(x0, x1);
            float S4s = upadd(fma2(px, w30p[7], S4p));
            float a3_23 = fmaf(0.5f, S1s + S4s, Uc);
            float a3_4  = S4s + Uc;
            // U for next step: slots (p+1..p+7) with wu[0..6], + u*wu[7]
            float Una = b30s, Unb = 0.0f;
#pragma unroll
            for (int k = 0; k < 6; k += 2) {
                Una = fmaf(up[(p + 1 + k) & 7], wu[k],     Una);
                Unb = fmaf(up[(p + 2 + k) & 7], wu[k + 1], Unb);
            }
            Una = fmaf(up[(p + 7) & 7], wu[6], Una);
            Unb = fmaf(u, wu[7], Unb);
            float Un = Una + Unb;
            float a3_1n = S4s + Un;        // k1-stage preact for step t+1

            // ---- three p3 evals in one broadcast round ----------------------
            float h2  = tanh_pre(a3_23);
            float h3  = tanh_pre(a3_4);
            float h1n = tanh_pre(a3_1n);
            float* buf = sbuf[wslot] + (p & 1) * 96;
            buf[lane]      = h2;
            buf[32 + lane] = h3;
            buf[64 + lane] = h1n;
            __syncwarp();
            // split accumulators: halve the serial fma2 chain depth
            ull C2a = b31p, C2b = 0ull, C3a = b31p, C3b = 0ull,
                C1a = b31p, C1b = 0ull;
            const ulonglong2* bq = reinterpret_cast<const ulonglong2*>(buf);
#pragma unroll
            for (int q = 0; q < 8; ++q) {
                ulonglong2 v2 = bq[q];
                C2a = fma2(v2.x, w31p[2 * q],     C2a);
                C2b = fma2(v2.y, w31p[2 * q + 1], C2b);
                ulonglong2 v3 = bq[8 + q];
                C3a = fma2(v3.x, w31p[2 * q],     C3a);
                C3b = fma2(v3.y, w31p[2 * q + 1], C3b);
                ulonglong2 v1 = bq[16 + q];
                C1a = fma2(v1.x, w31p[2 * q],     C1a);
                C1b = fma2(v1.y, w31p[2 * q + 1], C1b);
            }
            // q2: critical -> smem tree reduction (fast); q3, q1n: butterflies
            float q2 = tanh_pre(upadd(add2(C2a, C2b))) * w32;
            float* qbuf = sbuf[wslot] + 192;
            qbuf[lane] = q2;
            float q3 = tanh_pre(upadd(add2(C3a, C3b))) * w32;
            float q1 = tanh_pre(upadd(add2(C1a, C1b))) * w32;
            __syncwarp();
            ull s0, s1, s2, s3;
            {
                const ulonglong2* qv = reinterpret_cast<const ulonglong2*>(qbuf);
                ulonglong2 a0 = qv[0], a1 = qv[1], a2 = qv[2], a3 = qv[3],
                           a4 = qv[4], a5 = qv[5], a6 = qv[6], a7 = qv[7];
                s0 = add2(add2(a0.x, a0.y), add2(a1.x, a1.y));
                s1 = add2(add2(a2.x, a2.y), add2(a3.x, a3.y));
                s2 = add2(add2(a4.x, a4.y), add2(a5.x, a5.y));
                s3 = add2(add2(a6.x, a6.y), add2(a7.x, a7.y));
            }
            float r3s23 = upadd(add2(add2(s0, s1), add2(s2, s3))) + b32;
            float r3s4  = bfly(q3) + b32;
            float r3s1n = bfly(q1) + b32;

            // ---- RK4 k-chain: stage 1 uses carried r3s1 (starts early) -----
            float k10, k11; kof(x0, x1, r3s1, cafs, k10, k11);
            float xb0 = fmaf(0.5f, k10, x0), xb1 = fmaf(0.5f, k11, x1);
            float k20, k21; kof(xb0, xb1, r3s23, cafs, k20, k21);
            float xc0 = fmaf(0.5f, k20, x0), xc1 = fmaf(0.5f, k21, x1);
            float k30, k31; kof(xc0, xc1, r3s23, cafs, k30, k31);
            float xd0 = x0 + k30, xd1 = x1 + k31;
            float k40, k41; kof(xd0, xd1, r3s4, cafs, k40, k41);

            float nx0 = fmaf(k10 + 2.0f * (k20 + k30) + k40, 1.0f / 6.0f, x0);
            float nx1 = fmaf(k11 + 2.0f * (k21 + k31) + k41, 1.0f / 6.0f, x1);

            // ---- ring + pipeline updates (off critical path) ----------------
            xq[p & 7] = px;
            up[p & 7] = u;
            // history part of S4 for next step: slots (p+2+j), j=0..6
            ull S4n = 0ull;
#pragma unroll
            for (int j = 0; j < 7; ++j)
                S4n = fma2(xq[(p + 2 + j) & 7], w30p[j], S4n);
            S4p = S4n;
            S1s = S4s;
            Uc  = Un;
            r3s1 = r3s1n;
            x0 = nx0; x1 = nx1;
        }
    }
}

}  // namespace

extern "C" void kernel_launch(void* const* d_in, const int* in_sizes, int n_in,
                              void* d_out, int out_size) {
    (void)in_sizes; (void)n_in; (void)out_size;
    const float* useq = (const float*)d_in[0];
    const float* xz0  = (const float*)d_in[1];
    const float* r1W0 = (const float*)d_in[2];
    const float* r1b0 = (const float*)d_in[3];
    const float* r1W1 = (const float*)d_in[4];
    const float* r1b1 = (const float*)d_in[5];
    const float* r1W2 = (const float*)d_in[6];
    const float* r1b2 = (const float*)d_in[7];
    const float* r2W0 = (const float*)d_in[8];
    const float* r2b0 = (const float*)d_in[9];
    const float* r2W1 = (const float*)d_in[10];
    const float* r2b1 = (const float*)d_in[11];
    const float* r2W2 = (const float*)d_in[12];
    const float* r2b2 = (const float*)d_in[13];
    const float* r3W0 = (const float*)d_in[14];
    const float* r3b0 = (const float*)d_in[15];
    const float* r3W1 = (const float*)d_in[16];
    const float* r3b1 = (const float*)d_in[17];
    const float* r3W2 = (const float*)d_in[18];
    const float* r3b2 = (const float*)d_in[19];
    float* out = (float*)d_out;

    build_nodes<<<(2 * (kN + 1) + 127) / 128, 128>>>(
        r1W0, r1b0, r1W1, r1b1, r1W2, r1b2,
        r2W0, r2b0, r2W1, r2b1, r2W2, r2b2);
    build_coeffs<<<(kN + 127) / 128, 128>>>();
    rk4_kernel<<<kB / 4, 128>>>(useq, xz0,
                                r3W0, r3b0, r3W1, r3b1, r3W2, r3b2,
                                out);
}